// round 14
// baseline (speedup 1.0000x reference)
#include <cuda_runtime.h>
#include <cuda_fp16.h>
#include <math.h>
#include <stdint.h>

#define BB 4
#define TT 128
#define HH 1024
#define NN 300
#define VV 50265
#define EE 4800
#define BT (BB*TT)      // 512
#define KK2 (2*HH)      // 2048

// ---------------- scratch (device globals; no allocations) ----------------
__device__ __align__(16) __half g_hqH[BT*KK2];    // concat(hidden, qt) fp16
__device__ __align__(16) __half g_qeH[BT*KK2];    // concat(qt, te) fp16
__device__ float g_vh[HH], g_vs[HH], g_vx[HH];
__device__ float g_ps[BT], g_gg[BT], g_mg[BT];
__device__ float g_cp[BT*NN];
__device__ float g_graphT[BB*NN*NN];
__device__ float g_M[BT*NN];
__device__ float g_pg[BT*NN];

// ---------------- reductions ----------------
__device__ __forceinline__ float blk_reduce_sum(float v, float* sh) {
    int lane = threadIdx.x & 31, w = threadIdx.x >> 5;
    #pragma unroll
    for (int d = 16; d; d >>= 1) v += __shfl_down_sync(0xffffffffu, v, d);
    if (lane == 0) sh[w] = v;
    __syncthreads();
    int nw = (blockDim.x + 31) >> 5;
    if (threadIdx.x < 32) {
        float r = (lane < nw) ? sh[lane] : 0.f;
        #pragma unroll
        for (int d = 16; d; d >>= 1) r += __shfl_down_sync(0xffffffffu, r, d);
        if (lane == 0) sh[0] = r;
    }
    __syncthreads();
    return sh[0];
}

__device__ __forceinline__ float blk_reduce_max(float v, float* sh) {
    int lane = threadIdx.x & 31, w = threadIdx.x >> 5;
    #pragma unroll
    for (int d = 16; d; d >>= 1) v = fmaxf(v, __shfl_down_sync(0xffffffffu, v, d));
    if (lane == 0) sh[w] = v;
    __syncthreads();
    int nw = (blockDim.x + 31) >> 5;
    if (threadIdx.x < 32) {
        float r = (lane < nw) ? sh[lane] : -1e30f;
        #pragma unroll
        for (int d = 16; d; d >>= 1) r = fmaxf(r, __shfl_down_sync(0xffffffffu, r, d));
        if (lane == 0) sh[0] = r;
    }
    __syncthreads();
    return sh[0];
}

// ---------------- small kernels ----------------

__global__ void k_zero(float* out_cov) {
    int i = blockIdx.x * blockDim.x + threadIdx.x;
    if (i < BB*NN*NN) g_graphT[i] = 0.f;
    if (i < BB*NN)    out_cov[i]  = 0.f;
}

__global__ void k_vec(const float* __restrict__ Wh, const float* __restrict__ Ws,
                      const float* __restrict__ Wx, const float* __restrict__ Wps) {
    int gw   = (blockIdx.x * blockDim.x + threadIdx.x) >> 5;
    int lane = threadIdx.x & 31;
    if (gw >= 3 * HH) return;
    int mat = gw >> 10, row = gw & (HH - 1);
    const float* W = (mat == 0) ? Wh : (mat == 1) ? Ws : Wx;
    float s = 0.f;
    for (int o = lane; o < HH; o += 32) s += W[row * HH + o] * Wps[o];
    #pragma unroll
    for (int d = 16; d; d >>= 1) s += __shfl_down_sync(0xffffffffu, s, d);
    if (lane == 0) ((mat == 0) ? g_vh : (mat == 1) ? g_vs : g_vx)[row] = s;
}

// prefix kernel: hq fp16 conversion + the three per-token gates
__global__ void k_tok(const float* __restrict__ hs, const float* __restrict__ qt,
                      const float* __restrict__ te,
                      const float* __restrict__ bx, const float* __restrict__ Wps,
                      const float* __restrict__ bps,
                      const float* __restrict__ Wgg, const float* __restrict__ bgg,
                      const float* __restrict__ Wmg, const float* __restrict__ bmg,
                      float* out_ps) {
    int tok = blockIdx.x;
    int tid = threadIdx.x;
    const float* h = hs + (size_t)tok * HH;
    const float* q = qt + (size_t)tok * HH;
    const float* e = te + (size_t)tok * HH;
    float sp = 0.f, sg = 0.f, sm = 0.f;
    for (int k = tid; k < HH; k += blockDim.x) {
        float hv = h[k], qv = q[k], ev = e[k];
        g_hqH[(size_t)tok * KK2 + k]      = __float2half_rn(hv);
        g_hqH[(size_t)tok * KK2 + HH + k] = __float2half_rn(qv);
        sp += hv * g_vh[k] + qv * g_vs[k] + ev * g_vx[k] + bx[k] * Wps[k];
        sg += hv * Wgg[k] + qv * Wgg[HH + k];
        sm += hv * Wmg[k] + qv * Wmg[HH + k];
    }
    __shared__ float sh0[32], sh1[32], sh2[32];
    sp = blk_reduce_sum(sp, sh0);
    sg = blk_reduce_sum(sg, sh1);
    sm = blk_reduce_sum(sm, sh2);
    if (tid == 0) {
        float ps = 1.f / (1.f + expf(-(sp + bps[0])));
        float gg = 1.f / (1.f + expf(-(sg + bgg[0])));
        float mg = 1.f / (1.f + expf(-(sm + bmg[0])));
        g_ps[tok] = ps; g_gg[tok] = gg; g_mg[tok] = mg;
        out_ps[tok] = ps;
    }
}

// branch-B kernel: qe fp16 conversion (off critical path)
__global__ void k_qe(const float* __restrict__ qt, const float* __restrict__ te) {
    int tok = blockIdx.x;
    int tid = threadIdx.x;
    const float* q = qt + (size_t)tok * HH;
    const float* e = te + (size_t)tok * HH;
    for (int k = tid; k < HH; k += blockDim.x) {
        g_qeH[(size_t)tok * KK2 + k]      = __float2half_rn(q[k]);
        g_qeH[(size_t)tok * KK2 + HH + k] = __float2half_rn(e[k]);
    }
}

__global__ void k_edges(const int* __restrict__ edges) {
    int i = blockIdx.x * blockDim.x + threadIdx.x;
    if (i >= BB * EE) return;
    int b = i / EE, e = i % EE;
    int src = edges[b * 2 * EE + e];
    int dst = edges[b * 2 * EE + EE + e];
    atomicAdd(&g_graphT[b * NN * NN + dst * NN + src], 1.0f);
}

__global__ void k_m() {
    int b = blockIdx.x, n = threadIdx.x;
    if (n >= NN) return;
    float m = 0.f;
    for (int t = 0; t < TT; t++) {
        int bt = b * TT + t;
        float mg = g_mg[bt];
        m = g_cp[(size_t)bt * NN + n] * mg + m * (1.f - mg);
        g_M[(size_t)bt * NN + n] = m;
    }
}

#define GS_TT 16
__global__ void k_gsem() {
    __shared__ float Msh[GS_TT * NN];
    int b = blockIdx.x, t0 = blockIdx.y * GS_TT;
    int tid = threadIdx.x;
    for (int idx = tid; idx < GS_TT * NN; idx += blockDim.x) {
        int tt = idx / NN, j = idx % NN;
        Msh[tt * NN + j] = g_M[(size_t)(b * TT + t0 + tt) * NN + j];
    }
    __syncthreads();
    int i = tid;
    if (i >= NN) return;
    float acc[GS_TT];
    #pragma unroll
    for (int tt = 0; tt < GS_TT; tt++) acc[tt] = 0.f;
    const float* GT = g_graphT + (size_t)b * NN * NN;
    for (int j = 0; j < NN; j++) {
        float g = GT[(size_t)j * NN + i];
        #pragma unroll
        for (int tt = 0; tt < GS_TT; tt++) acc[tt] = fmaf(g, Msh[tt * NN + j], acc[tt]);
    }
    #pragma unroll
    for (int tt = 0; tt < GS_TT; tt++) {
        int bt = b * TT + t0 + tt;
        float gg = g_gg[bt];
        g_pg[(size_t)bt * NN + i] = g_cp[(size_t)bt * NN + i] * gg + acc[tt] * (1.f - gg);
    }
}

__global__ void k_cov(float* out_cov) {
    int bt = blockIdx.x;
    int b = bt / TT;
    int tid = threadIdx.x;
    float ps = g_ps[bt];
    float x = (tid < NN) ? g_pg[(size_t)bt * NN + tid] * ps : -1e30f;
    __shared__ float shm[32], shs[32];
    float mx = blk_reduce_max(x, shm);
    float e = (tid < NN) ? expf(x - mx) : 0.f;
    float s = blk_reduce_sum(e, shs);
    if (tid < NN) atomicAdd(&out_cov[b * NN + tid], e / s);
}

__global__ void k_scatter(const int* __restrict__ nidx, float* __restrict__ out) {
    int i = blockIdx.x * blockDim.x + threadIdx.x;
    if (i >= BT * NN) return;
    int bt = i / NN, n = i % NN;
    atomicAdd(&out[(size_t)bt * VV + nidx[n]], g_pg[i] * g_ps[bt]);
}

// ====== GEMM machinery: R11/R13 skeleton (BK=32, 3-stage A, 2-buffer B) ======
#define GH_BM 256
#define GH_BN 64
#define GH_NB (KK2 / 32)           // 64 k-blocks
#define GH_AP 80
#define GH_AST (GH_BM * GH_AP)     // 20480 per A stage
#define GH_BST (GH_BN * GH_AP)     // 5120 per B buffer
#define GH_SMEM (3 * GH_AST + 2 * GH_BST)   // 71680

__device__ __forceinline__ uint32_t smem_u32(const void* p) {
    uint32_t a;
    asm("{ .reg .u64 t; cvta.to.shared.u64 t, %1; cvt.u32.u64 %0, t; }" : "=r"(a) : "l"(p));
    return a;
}
__device__ __forceinline__ void cp16(uint32_t dst, const void* src) {
    asm volatile("cp.async.cg.shared.global [%0], [%1], 16;" :: "r"(dst), "l"(src));
}

#define LDSM_X4(r, addr) \
    asm volatile("ldmatrix.sync.aligned.m8n8.x4.shared.b16 {%0,%1,%2,%3}, [%4];" \
        : "=r"((r)[0]), "=r"((r)[1]), "=r"((r)[2]), "=r"((r)[3]) : "r"(addr))

#define HMMA(c, a, b0v, b1v) \
    asm volatile("mma.sync.aligned.m16n8k16.row.col.f32.f16.f16.f32 " \
        "{%0,%1,%2,%3}, {%4,%5,%6,%7}, {%8,%9}, {%0,%1,%2,%3};" \
        : "+f"((c)[0]), "+f"((c)[1]), "+f"((c)[2]), "+f"((c)[3]) \
        : "r"((a)[0]), "r"((a)[1]), "r"((a)[2]), "r"((a)[3]), "r"(b0v), "r"(b1v))

// Core mainloop. A = fp16 [BT,KK2]; B = f32 [KK2,LDB] converted inline.
// B LDG prefetch distance = 2 k-blocks. Out-of-range n clamped; epilogue
// never stores those columns.
template<int LDB>
__device__ __forceinline__ void gemm_core(const __half* __restrict__ Ah,
                                          const float* __restrict__ Bf,
                                          int m0, int n0, uint32_t sb,
                                          float (&acc)[4][4][4],
                                          uint32_t (&aoff)[4], uint32_t (&boff)[2]) {
    const int tid = threadIdx.x;
    const int bn = tid & 63;
    const int bq = tid >> 6;                 // 0..3, k = bq*8 .. bq*8+7
    const int nn = n0 + bn;
    const int nnc = (nn < LDB) ? nn : (LDB - 1);
    const uint32_t bsts = sb + 3u * GH_AST + (uint32_t)(bn * GH_AP + bq * 16);
    const __half* asrc = Ah + (size_t)m0 * KK2;

    auto cpA = [&](int kb, int s) {
        const uint32_t base = sb + (uint32_t)s * GH_AST;
        const size_t koff = (size_t)kb * 32;
        #pragma unroll
        for (int i = 0; i < 4; i++) {
            int idx = i * 256 + tid;           // 0..1023
            int m = idx >> 2, c = idx & 3;
            cp16(base + (uint32_t)(m * GH_AP + c * 16),
                 (const char*)(asrc + (size_t)m * KK2 + koff) + c * 16);
        }
        asm volatile("cp.async.commit_group;" ::: "memory");
    };
    auto ldgB = [&](float (&rB)[8], int kb) {
        const float* p = Bf + (size_t)(kb * 32 + bq * 8) * LDB + nnc;
        #pragma unroll
        for (int j = 0; j < 8; j++)
            rB[j] = p[(size_t)j * LDB];
    };
    auto stsB = [&](const float (&rB)[8], int buf) {
        __half2 h0 = __floats2half2_rn(rB[0], rB[1]);
        __half2 h1 = __floats2half2_rn(rB[2], rB[3]);
        __half2 h2 = __floats2half2_rn(rB[4], rB[5]);
        __half2 h3 = __floats2half2_rn(rB[6], rB[7]);
        asm volatile("st.shared.v4.b32 [%0], {%1, %2, %3, %4};"
                     :: "r"(bsts + (uint32_t)buf * GH_BST),
                        "r"(*(uint32_t*)&h0), "r"(*(uint32_t*)&h1),
                        "r"(*(uint32_t*)&h2), "r"(*(uint32_t*)&h3));
    };
    auto compute = [&](uint32_t As, uint32_t Bs) {
        #pragma unroll
        for (int ks = 0; ks < 2; ks++) {
            uint32_t a[4][4], bf[2][4];
            #pragma unroll
            for (int p = 0; p < 2; p++)
                LDSM_X4(bf[p], Bs + boff[p] + (uint32_t)(ks * 32));
            #pragma unroll
            for (int mi = 0; mi < 4; mi++)
                LDSM_X4(a[mi], As + aoff[mi] + (uint32_t)(ks * 32));
            #pragma unroll
            for (int mi = 0; mi < 4; mi++)
                #pragma unroll
                for (int p = 0; p < 2; p++) {
                    HMMA(acc[mi][2 * p],     a[mi], bf[p][0], bf[p][1]);
                    HMMA(acc[mi][2 * p + 1], a[mi], bf[p][2], bf[p][3]);
                }
        }
    };

    // ---- prologue: B prefetch distance 2, A 2 stages in flight ----
    float rBa[8], rBb[8];
    ldgB(rBa, 0);
    ldgB(rBb, 1);
    cpA(0, 0);
    cpA(1, 1);

    int stC = 0, stL = 2;     // compute stage / next-load stage (mod 3)
    #pragma unroll 1
    for (int kb = 0; kb < GH_NB; kb += 2) {
        // ---- even sub-iteration (B buffer 0) ----
        stsB(rBa, 0);
        if (kb + 2 < GH_NB) ldgB(rBa, kb + 2);
        asm volatile("cp.async.wait_group 1;" ::: "memory");   // cpA(kb) done
        __syncthreads();
        if (kb + 2 < GH_NB) {
            cpA(kb + 2, stL);
            stL = (stL == 2) ? 0 : stL + 1;
        }
        compute(sb + (uint32_t)stC * GH_AST, sb + 3u * GH_AST);
        stC = (stC == 2) ? 0 : stC + 1;

        // ---- odd sub-iteration (B buffer 1) ----
        stsB(rBb, 1);
        if (kb + 3 < GH_NB) ldgB(rBb, kb + 3);
        if (kb + 2 < GH_NB)
            asm volatile("cp.async.wait_group 1;" ::: "memory");
        else
            asm volatile("cp.async.wait_group 0;" ::: "memory");
        __syncthreads();
        if (kb + 3 < GH_NB) {
            cpA(kb + 3, stL);
            stL = (stL == 2) ? 0 : stL + 1;
        }
        compute(sb + (uint32_t)stC * GH_AST, sb + 3u * GH_AST + GH_BST);
        stC = (stC == 2) ? 0 : stC + 1;
    }
}

__device__ __forceinline__ void gemm_lane_setup(int lane, int wm, int wn,
                                                uint32_t (&aoff)[4], uint32_t (&boff)[2]) {
    const int a_row  = (lane & 7) + ((lane >> 3) & 1) * 8;
    const int a_koff = ((lane >> 4) & 1) * 16;
    const int b_row  = (lane & 7) + ((lane >> 4) & 1) * 8;
    const int b_koff = ((lane >> 3) & 1) * 16;
    #pragma unroll
    for (int mi = 0; mi < 4; mi++)
        aoff[mi] = (uint32_t)((wm + mi * 16 + a_row) * GH_AP + a_koff);
    #pragma unroll
    for (int p = 0; p < 2; p++)
        boff[p] = (uint32_t)((wn + p * 16 + b_row) * GH_AP + b_koff);
}

// ---- big GEMM: out = (hq @ Wg + bg) * (1 - ps) ----
__global__ __launch_bounds__(256, 2)
void k_gemm_h(const float* __restrict__ Wg, const float* __restrict__ bg,
              float* __restrict__ out) {
    extern __shared__ char smc[];
    const uint32_t sb = smem_u32(smc);
    const int lane = threadIdx.x & 31, wid = threadIdx.x >> 5;
    const int m0 = blockIdx.x * GH_BM;
    const int n0 = blockIdx.y * GH_BN;
    const int wm = (wid & 3) * 64, wn = (wid >> 2) * 32;
    const int g = lane >> 2, t = lane & 3;

    uint32_t aoff[4], boff[2];
    gemm_lane_setup(lane, wm, wn, aoff, boff);

    float acc[4][4][4];
    #pragma unroll
    for (int mi = 0; mi < 4; mi++)
        #pragma unroll
        for (int nj = 0; nj < 4; nj++)
            #pragma unroll
            for (int q = 0; q < 4; q++) acc[mi][nj][q] = 0.f;

    gemm_core<VV>(g_hqH, Wg, m0, n0, sb, acc, aoff, boff);

    #pragma unroll
    for (int mi = 0; mi < 4; mi++) {
        int m = m0 + wm + mi * 16 + g;
        float s0 = 1.f - g_ps[m];
        float s1 = 1.f - g_ps[m + 8];
        #pragma unroll
        for (int nj = 0; nj < 4; nj++) {
            int n = n0 + wn + nj * 8 + t * 2;
            if (n < VV) {
                float bgv = bg[n];
                out[(size_t)m * VV + n]       = (acc[mi][nj][0] + bgv) * s0;
                out[(size_t)(m + 8) * VV + n] = (acc[mi][nj][2] + bgv) * s1;
            }
            if (n + 1 < VV) {
                float bgv = bg[n + 1];
                out[(size_t)m * VV + n + 1]       = (acc[mi][nj][1] + bgv) * s0;
                out[(size_t)(m + 8) * VV + n + 1] = (acc[mi][nj][3] + bgv) * s1;
            }
        }
    }
}

// ---- cp GEMM: g_cp = qe @ Wc + bc ----
__global__ __launch_bounds__(256, 2)
void k_cp_h(const float* __restrict__ Wc, const float* __restrict__ bc) {
    extern __shared__ char smc[];
    const uint32_t sb = smem_u32(smc);
    const int lane = threadIdx.x & 31, wid = threadIdx.x >> 5;
    const int m0 = blockIdx.x * GH_BM;
    const int n0 = blockIdx.y * GH_BN;
    const int wm = (wid & 3) * 64, wn = (wid >> 2) * 32;
    const int g = lane >> 2, t = lane & 3;

    uint32_t aoff[4], boff[2];
    gemm_lane_setup(lane, wm, wn, aoff, boff);

    float acc[4][4][4];
    #pragma unroll
    for (int mi = 0; mi < 4; mi++)
        #pragma unroll
        for (int nj = 0; nj < 4; nj++)
            #pragma unroll
            for (int q = 0; q < 4; q++) acc[mi][nj][q] = 0.f;

    gemm_core<NN>(g_qeH, Wc, m0, n0, sb, acc, aoff, boff);

    #pragma unroll
    for (int mi = 0; mi < 4; mi++) {
        int m = m0 + wm + mi * 16 + g;
        #pragma unroll
        for (int nj = 0; nj < 4; nj++) {
            int n = n0 + wn + nj * 8 + t * 2;
            if (n < NN) {
                g_cp[(size_t)m * NN + n]       = acc[mi][nj][0] + bc[n];
                g_cp[(size_t)(m + 8) * NN + n] = acc[mi][nj][2] + bc[n];
            }
            if (n + 1 < NN) {
                g_cp[(size_t)m * NN + n + 1]       = acc[mi][nj][1] + bc[n + 1];
                g_cp[(size_t)(m + 8) * NN + n + 1] = acc[mi][nj][3] + bc[n + 1];
            }
        }
    }
}

// ------- launch: fork/join with HIGH-PRIORITY side stream -------
// GigaThread dispatches grids in launch order at equal priority, so the
// 1572-CTA GEMM starves the side stream until its last wave (measured ~92us
// serialized tail in R11-R13). A high-priority side stream lets branch-B CTAs
// claim SM slots as GEMM CTAs retire, hiding branch B entirely.
extern "C" void kernel_launch(void* const* d_in, const int* in_sizes, int n_in,
                              void* d_out, int out_size) {
    const float* hs   = (const float*)d_in[0];
    const float* qt   = (const float*)d_in[1];
    const float* te   = (const float*)d_in[2];
    const int*   edges= (const int*)  d_in[3];
    const int*   nidx = (const int*)  d_in[4];
    const float* Wg   = (const float*)d_in[5];
    const float* bg   = (const float*)d_in[6];
    const float* Wh   = (const float*)d_in[7];
    const float* Ws   = (const float*)d_in[8];
    const float* Wx   = (const float*)d_in[9];
    const float* bx   = (const float*)d_in[10];
    const float* Wps  = (const float*)d_in[11];
    const float* bps  = (const float*)d_in[12];
    const float* Wc   = (const float*)d_in[13];
    const float* bc   = (const float*)d_in[14];
    const float* Wgg  = (const float*)d_in[15];
    const float* bgg  = (const float*)d_in[16];
    const float* Wmg  = (const float*)d_in[17];
    const float* bmg  = (const float*)d_in[18];

    float* out    = (float*)d_out;
    float* outCov = out + (size_t)BT * VV;
    float* outPs  = outCov + BB * NN;

    cudaFuncSetAttribute(k_gemm_h, cudaFuncAttributeMaxDynamicSharedMemorySize, GH_SMEM);
    cudaFuncSetAttribute(k_cp_h,   cudaFuncAttributeMaxDynamicSharedMemorySize, GH_SMEM);

    // Fresh high-priority side stream + events each call (host objects only).
    int prLo = 0, prHi = 0;
    cudaDeviceGetStreamPriorityRange(&prLo, &prHi);   // prHi = greatest priority
    cudaStream_t s1;
    cudaStreamCreateWithPriority(&s1, cudaStreamNonBlocking, prHi);
    cudaEvent_t evFork, evJoin;
    cudaEventCreateWithFlags(&evFork, cudaEventDisableTiming);
    cudaEventCreateWithFlags(&evJoin, cudaEventDisableTiming);

    // ---- main stream prefix ----
    k_vec<<<(3 * HH * 32 + 255) / 256, 256>>>(Wh, Ws, Wx, Wps);
    k_tok<<<BT, 256>>>(hs, qt, te, bx, Wps, bps, Wgg, bgg, Wmg, bmg, outPs);
    cudaEventRecord(evFork, 0);
    cudaStreamWaitEvent(s1, evFork, 0);

    // ---- branch B head (side stream, before GEMM launch) ----
    k_zero<<<(BB*NN*NN + 255) / 256, 256, 0, s1>>>(outCov);
    k_qe<<<BT, 256, 0, s1>>>(qt, te);
    k_edges<<<(BB*EE + 255) / 256, 256, 0, s1>>>(edges);

    // ---- branch A (main stream): big GEMM ----
    k_gemm_h<<<dim3(BT / GH_BM, (VV + GH_BN - 1) / GH_BN), 256, GH_SMEM>>>(Wg, bg, out);

    // ---- branch B tail (side stream) ----
    k_cp_h<<<dim3(BT / GH_BM, (NN + GH_BN - 1) / GH_BN), 256, GH_SMEM, s1>>>(Wc, bc);
    k_m<<<BB, 320, 0, s1>>>();
    k_gsem<<<dim3(BB, TT / GS_TT), 320, 0, s1>>>();
    k_cov<<<BT, 320, 0, s1>>>(outCov);
    cudaEventRecord(evJoin, s1);

    // ---- join ----
    cudaStreamWaitEvent(0, evJoin, 0);
    k_scatter<<<(BT*NN + 255) / 256, 256>>>(nidx, out);
}

// round 15
// speedup vs baseline: 1.0191x; 1.0191x over previous
#include <cuda_runtime.h>
#include <cuda_fp16.h>
#include <math.h>
#include <stdint.h>

#define BB 4
#define TT 128
#define HH 1024
#define NN 300
#define VV 50265
#define EE 4800
#define BT (BB*TT)      // 512
#define KK2 (2*HH)      // 2048

// ---------------- scratch (device globals; no allocations) ----------------
__device__ __align__(16) __half g_hqH[BT*KK2];    // concat(hidden, qt) fp16
__device__ __align__(16) __half g_qeH[BT*KK2];    // concat(qt, te) fp16
__device__ float g_vh[HH], g_vs[HH], g_vx[HH];
__device__ float g_ps[BT], g_gg[BT], g_mg[BT];
__device__ float g_cp[BT*NN];
__device__ float g_graphT[BB*NN*NN];
__device__ float g_M[BT*NN];
__device__ float g_pg[BT*NN];

// ---------------- reductions ----------------
__device__ __forceinline__ float blk_reduce_sum(float v, float* sh) {
    int lane = threadIdx.x & 31, w = threadIdx.x >> 5;
    #pragma unroll
    for (int d = 16; d; d >>= 1) v += __shfl_down_sync(0xffffffffu, v, d);
    if (lane == 0) sh[w] = v;
    __syncthreads();
    int nw = (blockDim.x + 31) >> 5;
    if (threadIdx.x < 32) {
        float r = (lane < nw) ? sh[lane] : 0.f;
        #pragma unroll
        for (int d = 16; d; d >>= 1) r += __shfl_down_sync(0xffffffffu, r, d);
        if (lane == 0) sh[0] = r;
    }
    __syncthreads();
    return sh[0];
}

__device__ __forceinline__ float blk_reduce_max(float v, float* sh) {
    int lane = threadIdx.x & 31, w = threadIdx.x >> 5;
    #pragma unroll
    for (int d = 16; d; d >>= 1) v = fmaxf(v, __shfl_down_sync(0xffffffffu, v, d));
    if (lane == 0) sh[w] = v;
    __syncthreads();
    int nw = (blockDim.x + 31) >> 5;
    if (threadIdx.x < 32) {
        float r = (lane < nw) ? sh[lane] : -1e30f;
        #pragma unroll
        for (int d = 16; d; d >>= 1) r = fmaxf(r, __shfl_down_sync(0xffffffffu, r, d));
        if (lane == 0) sh[0] = r;
    }
    __syncthreads();
    return sh[0];
}

// ---------------- small kernels ----------------

__global__ void k_zero(float* out_cov) {
    int i = blockIdx.x * blockDim.x + threadIdx.x;
    if (i < BB*NN*NN) g_graphT[i] = 0.f;
    if (i < BB*NN)    out_cov[i]  = 0.f;
}

__global__ void k_vec(const float* __restrict__ Wh, const float* __restrict__ Ws,
                      const float* __restrict__ Wx, const float* __restrict__ Wps) {
    int gw   = (blockIdx.x * blockDim.x + threadIdx.x) >> 5;
    int lane = threadIdx.x & 31;
    if (gw >= 3 * HH) return;
    int mat = gw >> 10, row = gw & (HH - 1);
    const float* W = (mat == 0) ? Wh : (mat == 1) ? Ws : Wx;
    float s = 0.f;
    for (int o = lane; o < HH; o += 32) s += W[row * HH + o] * Wps[o];
    #pragma unroll
    for (int d = 16; d; d >>= 1) s += __shfl_down_sync(0xffffffffu, s, d);
    if (lane == 0) ((mat == 0) ? g_vh : (mat == 1) ? g_vs : g_vx)[row] = s;
}

// prefix kernel: hq fp16 conversion + the three per-token gates
__global__ void k_tok(const float* __restrict__ hs, const float* __restrict__ qt,
                      const float* __restrict__ te,
                      const float* __restrict__ bx, const float* __restrict__ Wps,
                      const float* __restrict__ bps,
                      const float* __restrict__ Wgg, const float* __restrict__ bgg,
                      const float* __restrict__ Wmg, const float* __restrict__ bmg,
                      float* out_ps) {
    int tok = blockIdx.x;
    int tid = threadIdx.x;
    const float* h = hs + (size_t)tok * HH;
    const float* q = qt + (size_t)tok * HH;
    const float* e = te + (size_t)tok * HH;
    float sp = 0.f, sg = 0.f, sm = 0.f;
    for (int k = tid; k < HH; k += blockDim.x) {
        float hv = h[k], qv = q[k], ev = e[k];
        g_hqH[(size_t)tok * KK2 + k]      = __float2half_rn(hv);
        g_hqH[(size_t)tok * KK2 + HH + k] = __float2half_rn(qv);
        sp += hv * g_vh[k] + qv * g_vs[k] + ev * g_vx[k] + bx[k] * Wps[k];
        sg += hv * Wgg[k] + qv * Wgg[HH + k];
        sm += hv * Wmg[k] + qv * Wmg[HH + k];
    }
    __shared__ float sh0[32], sh1[32], sh2[32];
    sp = blk_reduce_sum(sp, sh0);
    sg = blk_reduce_sum(sg, sh1);
    sm = blk_reduce_sum(sm, sh2);
    if (tid == 0) {
        float ps = 1.f / (1.f + expf(-(sp + bps[0])));
        float gg = 1.f / (1.f + expf(-(sg + bgg[0])));
        float mg = 1.f / (1.f + expf(-(sm + bmg[0])));
        g_ps[tok] = ps; g_gg[tok] = gg; g_mg[tok] = mg;
        out_ps[tok] = ps;
    }
}

// prefix kernel: qe fp16 conversion (must precede fused GEMM)
__global__ void k_qe(const float* __restrict__ qt, const float* __restrict__ te) {
    int tok = blockIdx.x;
    int tid = threadIdx.x;
    const float* q = qt + (size_t)tok * HH;
    const float* e = te + (size_t)tok * HH;
    for (int k = tid; k < HH; k += blockDim.x) {
        g_qeH[(size_t)tok * KK2 + k]      = __float2half_rn(q[k]);
        g_qeH[(size_t)tok * KK2 + HH + k] = __float2half_rn(e[k]);
    }
}

__global__ void k_edges(const int* __restrict__ edges) {
    int i = blockIdx.x * blockDim.x + threadIdx.x;
    if (i >= BB * EE) return;
    int b = i / EE, e = i % EE;
    int src = edges[b * 2 * EE + e];
    int dst = edges[b * 2 * EE + EE + e];
    atomicAdd(&g_graphT[b * NN * NN + dst * NN + src], 1.0f);
}

__global__ void k_m() {
    int b = blockIdx.x, n = threadIdx.x;
    if (n >= NN) return;
    float m = 0.f;
    for (int t = 0; t < TT; t++) {
        int bt = b * TT + t;
        float mg = g_mg[bt];
        m = g_cp[(size_t)bt * NN + n] * mg + m * (1.f - mg);
        g_M[(size_t)bt * NN + n] = m;
    }
}

#define GS_TT 16
__global__ void k_gsem() {
    __shared__ float Msh[GS_TT * NN];
    int b = blockIdx.x, t0 = blockIdx.y * GS_TT;
    int tid = threadIdx.x;
    for (int idx = tid; idx < GS_TT * NN; idx += blockDim.x) {
        int tt = idx / NN, j = idx % NN;
        Msh[tt * NN + j] = g_M[(size_t)(b * TT + t0 + tt) * NN + j];
    }
    __syncthreads();
    int i = tid;
    if (i >= NN) return;
    float acc[GS_TT];
    #pragma unroll
    for (int tt = 0; tt < GS_TT; tt++) acc[tt] = 0.f;
    const float* GT = g_graphT + (size_t)b * NN * NN;
    for (int j = 0; j < NN; j++) {
        float g = GT[(size_t)j * NN + i];
        #pragma unroll
        for (int tt = 0; tt < GS_TT; tt++) acc[tt] = fmaf(g, Msh[tt * NN + j], acc[tt]);
    }
    #pragma unroll
    for (int tt = 0; tt < GS_TT; tt++) {
        int bt = b * TT + t0 + tt;
        float gg = g_gg[bt];
        g_pg[(size_t)bt * NN + i] = g_cp[(size_t)bt * NN + i] * gg + acc[tt] * (1.f - gg);
    }
}

__global__ void k_cov(float* out_cov) {
    int bt = blockIdx.x;
    int b = bt / TT;
    int tid = threadIdx.x;
    float ps = g_ps[bt];
    float x = (tid < NN) ? g_pg[(size_t)bt * NN + tid] * ps : -1e30f;
    __shared__ float shm[32], shs[32];
    float mx = blk_reduce_max(x, shm);
    float e = (tid < NN) ? expf(x - mx) : 0.f;
    float s = blk_reduce_sum(e, shs);
    if (tid < NN) atomicAdd(&out_cov[b * NN + tid], e / s);
}

__global__ void k_scatter(const int* __restrict__ nidx, float* __restrict__ out) {
    int i = blockIdx.x * blockDim.x + threadIdx.x;
    if (i >= BT * NN) return;
    int bt = i / NN, n = i % NN;
    atomicAdd(&out[(size_t)bt * VV + nidx[n]], g_pg[i] * g_ps[bt]);
}

// ====== GEMM machinery (R13 skeleton, unchanged) ======
#define GH_BM 256
#define GH_BN 64
#define GH_NB (KK2 / 32)           // 64 k-blocks
#define GH_AP 80
#define GH_AST (GH_BM * GH_AP)     // 20480 per A stage
#define GH_BST (GH_BN * GH_AP)     // 5120 per B buffer
#define GH_SMEM (3 * GH_AST + 2 * GH_BST)   // 71680
#define GH_NVT ((VV + GH_BN - 1) / GH_BN)   // 786 big-GEMM n tiles
#define GH_NCT ((NN + GH_BN - 1) / GH_BN)   // 5 cp-GEMM n tiles

__device__ __forceinline__ uint32_t smem_u32(const void* p) {
    uint32_t a;
    asm("{ .reg .u64 t; cvta.to.shared.u64 t, %1; cvt.u32.u64 %0, t; }" : "=r"(a) : "l"(p));
    return a;
}
__device__ __forceinline__ void cp16(uint32_t dst, const void* src) {
    asm volatile("cp.async.cg.shared.global [%0], [%1], 16;" :: "r"(dst), "l"(src));
}

#define LDSM_X4(r, addr) \
    asm volatile("ldmatrix.sync.aligned.m8n8.x4.shared.b16 {%0,%1,%2,%3}, [%4];" \
        : "=r"((r)[0]), "=r"((r)[1]), "=r"((r)[2]), "=r"((r)[3]) : "r"(addr))

#define HMMA(c, a, b0v, b1v) \
    asm volatile("mma.sync.aligned.m16n8k16.row.col.f32.f16.f16.f32 " \
        "{%0,%1,%2,%3}, {%4,%5,%6,%7}, {%8,%9}, {%0,%1,%2,%3};" \
        : "+f"((c)[0]), "+f"((c)[1]), "+f"((c)[2]), "+f"((c)[3]) \
        : "r"((a)[0]), "r"((a)[1]), "r"((a)[2]), "r"((a)[3]), "r"(b0v), "r"(b1v))

// Core mainloop. A = fp16 [BT,KK2]; B = f32 [KK2,LDB] converted inline.
// B LDG prefetch distance = 2 k-blocks. Out-of-range n clamped; epilogue
// never stores those columns.
template<int LDB>
__device__ __forceinline__ void gemm_core(const __half* __restrict__ Ah,
                                          const float* __restrict__ Bf,
                                          int m0, int n0, uint32_t sb,
                                          float (&acc)[4][4][4],
                                          uint32_t (&aoff)[4], uint32_t (&boff)[2]) {
    const int tid = threadIdx.x;
    const int bn = tid & 63;
    const int bq = tid >> 6;                 // 0..3, k = bq*8 .. bq*8+7
    const int nn = n0 + bn;
    const int nnc = (nn < LDB) ? nn : (LDB - 1);
    const uint32_t bsts = sb + 3u * GH_AST + (uint32_t)(bn * GH_AP + bq * 16);
    const __half* asrc = Ah + (size_t)m0 * KK2;

    auto cpA = [&](int kb, int s) {
        const uint32_t base = sb + (uint32_t)s * GH_AST;
        const size_t koff = (size_t)kb * 32;
        #pragma unroll
        for (int i = 0; i < 4; i++) {
            int idx = i * 256 + tid;           // 0..1023
            int m = idx >> 2, c = idx & 3;
            cp16(base + (uint32_t)(m * GH_AP + c * 16),
                 (const char*)(asrc + (size_t)m * KK2 + koff) + c * 16);
        }
        asm volatile("cp.async.commit_group;" ::: "memory");
    };
    auto ldgB = [&](float (&rB)[8], int kb) {
        const float* p = Bf + (size_t)(kb * 32 + bq * 8) * LDB + nnc;
        #pragma unroll
        for (int j = 0; j < 8; j++)
            rB[j] = p[(size_t)j * LDB];
    };
    auto stsB = [&](const float (&rB)[8], int buf) {
        __half2 h0 = __floats2half2_rn(rB[0], rB[1]);
        __half2 h1 = __floats2half2_rn(rB[2], rB[3]);
        __half2 h2 = __floats2half2_rn(rB[4], rB[5]);
        __half2 h3 = __floats2half2_rn(rB[6], rB[7]);
        asm volatile("st.shared.v4.b32 [%0], {%1, %2, %3, %4};"
                     :: "r"(bsts + (uint32_t)buf * GH_BST),
                        "r"(*(uint32_t*)&h0), "r"(*(uint32_t*)&h1),
                        "r"(*(uint32_t*)&h2), "r"(*(uint32_t*)&h3));
    };
    auto compute = [&](uint32_t As, uint32_t Bs) {
        #pragma unroll
        for (int ks = 0; ks < 2; ks++) {
            uint32_t a[4][4], bf[2][4];
            #pragma unroll
            for (int p = 0; p < 2; p++)
                LDSM_X4(bf[p], Bs + boff[p] + (uint32_t)(ks * 32));
            #pragma unroll
            for (int mi = 0; mi < 4; mi++)
                LDSM_X4(a[mi], As + aoff[mi] + (uint32_t)(ks * 32));
            #pragma unroll
            for (int mi = 0; mi < 4; mi++)
                #pragma unroll
                for (int p = 0; p < 2; p++) {
                    HMMA(acc[mi][2 * p],     a[mi], bf[p][0], bf[p][1]);
                    HMMA(acc[mi][2 * p + 1], a[mi], bf[p][2], bf[p][3]);
                }
        }
    };

    // ---- prologue: B prefetch distance 2, A 2 stages in flight ----
    float rBa[8], rBb[8];
    ldgB(rBa, 0);
    ldgB(rBb, 1);
    cpA(0, 0);
    cpA(1, 1);

    int stC = 0, stL = 2;     // compute stage / next-load stage (mod 3)
    #pragma unroll 1
    for (int kb = 0; kb < GH_NB; kb += 2) {
        // ---- even sub-iteration (B buffer 0) ----
        stsB(rBa, 0);
        if (kb + 2 < GH_NB) ldgB(rBa, kb + 2);
        asm volatile("cp.async.wait_group 1;" ::: "memory");   // cpA(kb) done
        __syncthreads();
        if (kb + 2 < GH_NB) {
            cpA(kb + 2, stL);
            stL = (stL == 2) ? 0 : stL + 1;
        }
        compute(sb + (uint32_t)stC * GH_AST, sb + 3u * GH_AST);
        stC = (stC == 2) ? 0 : stC + 1;

        // ---- odd sub-iteration (B buffer 1) ----
        stsB(rBb, 1);
        if (kb + 3 < GH_NB) ldgB(rBb, kb + 3);
        if (kb + 2 < GH_NB)
            asm volatile("cp.async.wait_group 1;" ::: "memory");
        else
            asm volatile("cp.async.wait_group 0;" ::: "memory");
        __syncthreads();
        if (kb + 3 < GH_NB) {
            cpA(kb + 3, stL);
            stL = (stL == 2) ? 0 : stL + 1;
        }
        compute(sb + (uint32_t)stC * GH_AST, sb + 3u * GH_AST + GH_BST);
        stC = (stC == 2) ? 0 : stC + 1;
    }
}

__device__ __forceinline__ void gemm_lane_setup(int lane, int wm, int wn,
                                                uint32_t (&aoff)[4], uint32_t (&boff)[2]) {
    const int a_row  = (lane & 7) + ((lane >> 3) & 1) * 8;
    const int a_koff = ((lane >> 4) & 1) * 16;
    const int b_row  = (lane & 7) + ((lane >> 4) & 1) * 8;
    const int b_koff = ((lane >> 3) & 1) * 16;
    #pragma unroll
    for (int mi = 0; mi < 4; mi++)
        aoff[mi] = (uint32_t)((wm + mi * 16 + a_row) * GH_AP + a_koff);
    #pragma unroll
    for (int p = 0; p < 2; p++)
        boff[p] = (uint32_t)((wn + p * 16 + b_row) * GH_AP + b_koff);
}

// ---- FUSED GEMM: blockIdx.y < GH_NVT -> vocab GEMM (out);
//                  blockIdx.y >= GH_NVT -> cp GEMM (g_cp).
// cp tiles ride inside the big GEMM's wave schedule: no extra wave, which
// removes the ~77us serialized k_cp_h wave measured in R11-R14.
__global__ __launch_bounds__(256, 2)
void k_gemm_f(const float* __restrict__ Wg, const float* __restrict__ bg,
              const float* __restrict__ Wc, const float* __restrict__ bc,
              float* __restrict__ out) {
    extern __shared__ char smc[];
    const uint32_t sb = smem_u32(smc);
    const int lane = threadIdx.x & 31, wid = threadIdx.x >> 5;
    const int m0 = blockIdx.x * GH_BM;
    const int wm = (wid & 3) * 64, wn = (wid >> 2) * 32;
    const int g = lane >> 2, t = lane & 3;

    uint32_t aoff[4], boff[2];
    gemm_lane_setup(lane, wm, wn, aoff, boff);

    float acc[4][4][4];
    #pragma unroll
    for (int mi = 0; mi < 4; mi++)
        #pragma unroll
        for (int nj = 0; nj < 4; nj++)
            #pragma unroll
            for (int q = 0; q < 4; q++) acc[mi][nj][q] = 0.f;

    if (blockIdx.y < GH_NVT) {
        // ---------- vocab GEMM path ----------
        const int n0 = blockIdx.y * GH_BN;
        gemm_core<VV>(g_hqH, Wg, m0, n0, sb, acc, aoff, boff);

        #pragma unroll
        for (int mi = 0; mi < 4; mi++) {
            int m = m0 + wm + mi * 16 + g;
            float s0 = 1.f - g_ps[m];
            float s1 = 1.f - g_ps[m + 8];
            #pragma unroll
            for (int nj = 0; nj < 4; nj++) {
                int n = n0 + wn + nj * 8 + t * 2;
                if (n < VV) {
                    float bgv = bg[n];
                    out[(size_t)m * VV + n]       = (acc[mi][nj][0] + bgv) * s0;
                    out[(size_t)(m + 8) * VV + n] = (acc[mi][nj][2] + bgv) * s1;
                }
                if (n + 1 < VV) {
                    float bgv = bg[n + 1];
                    out[(size_t)m * VV + n + 1]       = (acc[mi][nj][1] + bgv) * s0;
                    out[(size_t)(m + 8) * VV + n + 1] = (acc[mi][nj][3] + bgv) * s1;
                }
            }
        }
    } else {
        // ---------- cp GEMM path: g_cp = qe @ Wc + bc ----------
        const int n0 = (blockIdx.y - GH_NVT) * GH_BN;
        gemm_core<NN>(g_qeH, Wc, m0, n0, sb, acc, aoff, boff);

        #pragma unroll
        for (int mi = 0; mi < 4; mi++) {
            int m = m0 + wm + mi * 16 + g;
            #pragma unroll
            for (int nj = 0; nj < 4; nj++) {
                int n = n0 + wn + nj * 8 + t * 2;
                if (n < NN) {
                    g_cp[(size_t)m * NN + n]       = acc[mi][nj][0] + bc[n];
                    g_cp[(size_t)(m + 8) * NN + n] = acc[mi][nj][2] + bc[n];
                }
                if (n + 1 < NN) {
                    g_cp[(size_t)m * NN + n + 1]       = acc[mi][nj][1] + bc[n + 1];
                    g_cp[(size_t)(m + 8) * NN + n + 1] = acc[mi][nj][3] + bc[n + 1];
                }
            }
        }
    }
}

// ---------------- launch ----------------
extern "C" void kernel_launch(void* const* d_in, const int* in_sizes, int n_in,
                              void* d_out, int out_size) {
    const float* hs   = (const float*)d_in[0];
    const float* qt   = (const float*)d_in[1];
    const float* te   = (const float*)d_in[2];
    const int*   edges= (const int*)  d_in[3];
    const int*   nidx = (const int*)  d_in[4];
    const float* Wg   = (const float*)d_in[5];
    const float* bg   = (const float*)d_in[6];
    const float* Wh   = (const float*)d_in[7];
    const float* Ws   = (const float*)d_in[8];
    const float* Wx   = (const float*)d_in[9];
    const float* bx   = (const float*)d_in[10];
    const float* Wps  = (const float*)d_in[11];
    const float* bps  = (const float*)d_in[12];
    const float* Wc   = (const float*)d_in[13];
    const float* bc   = (const float*)d_in[14];
    const float* Wgg  = (const float*)d_in[15];
    const float* bgg  = (const float*)d_in[16];
    const float* Wmg  = (const float*)d_in[17];
    const float* bmg  = (const float*)d_in[18];

    float* out    = (float*)d_out;
    float* outCov = out + (size_t)BT * VV;
    float* outPs  = outCov + BB * NN;

    cudaFuncSetAttribute(k_gemm_f, cudaFuncAttributeMaxDynamicSharedMemorySize, GH_SMEM);

    // Fresh side stream + events each call (host objects only; no device mem).
    cudaStream_t s1;
    cudaStreamCreateWithFlags(&s1, cudaStreamNonBlocking);
    cudaEvent_t evFork, evB;
    cudaEventCreateWithFlags(&evFork, cudaEventDisableTiming);
    cudaEventCreateWithFlags(&evB, cudaEventDisableTiming);

    // ---- prefix (main stream): everything the fused GEMM needs ----
    k_vec<<<(3 * HH * 32 + 255) / 256, 256>>>(Wh, Ws, Wx, Wps);
    k_tok<<<BT, 256>>>(hs, qt, te, bx, Wps, bps, Wgg, bgg, Wmg, bmg, outPs);
    k_qe<<<BT, 256>>>(qt, te);
    cudaEventRecord(evFork, 0);
    cudaStreamWaitEvent(s1, evFork, 0);

    // ---- side stream: graph build + zeroing (overlaps GEMM) ----
    k_zero<<<(BB*NN*NN + 255) / 256, 256, 0, s1>>>(outCov);
    k_edges<<<(BB*EE + 255) / 256, 256, 0, s1>>>(edges);
    cudaEventRecord(evB, s1);

    // ---- fused GEMM (vocab + cp tiles in one grid) ----
    k_gemm_f<<<dim3(BT / GH_BM, GH_NVT + GH_NCT), 256, GH_SMEM>>>(Wg, bg, Wc, bc, out);

    // ---- tail (main stream): recurrence -> graph matmul -> coverage ----
    k_m<<<BB, 320>>>();
    cudaStreamWaitEvent(0, evB, 0);           // graphT ready
    k_gsem<<<dim3(BB, TT / GS_TT), 320>>>();
    k_cov<<<BT, 320>>>(outCov);
    k_scatter<<<(BT*NN + 255) / 256, 256>>>(nidx, out);
}

// round 16
// speedup vs baseline: 1.0772x; 1.0570x over previous
#include <cuda_runtime.h>
#include <cuda_fp16.h>
#include <math.h>
#include <stdint.h>

#define BB 4
#define TT 128
#define HH 1024
#define NN 300
#define VV 50265
#define EE 4800
#define BT (BB*TT)      // 512
#define KK2 (2*HH)      // 2048

// ---------------- scratch (device globals; no allocations) ----------------
__device__ __align__(16) __half g_hqH[BT*KK2];    // concat(hidden, qt) fp16
__device__ __align__(16) __half g_qeH[BT*KK2];    // concat(qt, te) fp16
__device__ float g_vh[HH], g_vs[HH], g_vx[HH];
__device__ float g_ps[BT], g_gg[BT], g_mg[BT];
__device__ float g_cp[BT*NN];
__device__ float g_graphT[BB*NN*NN];
__device__ float g_M[BT*NN];
__device__ float g_pg[BT*NN];

// ---------------- reductions ----------------
__device__ __forceinline__ float blk_reduce_sum(float v, float* sh) {
    int lane = threadIdx.x & 31, w = threadIdx.x >> 5;
    #pragma unroll
    for (int d = 16; d; d >>= 1) v += __shfl_down_sync(0xffffffffu, v, d);
    if (lane == 0) sh[w] = v;
    __syncthreads();
    int nw = (blockDim.x + 31) >> 5;
    if (threadIdx.x < 32) {
        float r = (lane < nw) ? sh[lane] : 0.f;
        #pragma unroll
        for (int d = 16; d; d >>= 1) r += __shfl_down_sync(0xffffffffu, r, d);
        if (lane == 0) sh[0] = r;
    }
    __syncthreads();
    return sh[0];
}

__device__ __forceinline__ float blk_reduce_max(float v, float* sh) {
    int lane = threadIdx.x & 31, w = threadIdx.x >> 5;
    #pragma unroll
    for (int d = 16; d; d >>= 1) v = fmaxf(v, __shfl_down_sync(0xffffffffu, v, d));
    if (lane == 0) sh[w] = v;
    __syncthreads();
    int nw = (blockDim.x + 31) >> 5;
    if (threadIdx.x < 32) {
        float r = (lane < nw) ? sh[lane] : -1e30f;
        #pragma unroll
        for (int d = 16; d; d >>= 1) r = fmaxf(r, __shfl_down_sync(0xffffffffu, r, d));
        if (lane == 0) sh[0] = r;
    }
    __syncthreads();
    return sh[0];
}

// ---------------- small kernels ----------------

__global__ void k_zero(float* out_cov) {
    int i = blockIdx.x * blockDim.x + threadIdx.x;
    if (i < BB*NN*NN) g_graphT[i] = 0.f;
    if (i < BB*NN)    out_cov[i]  = 0.f;
}

__global__ void k_vec(const float* __restrict__ Wh, const float* __restrict__ Ws,
                      const float* __restrict__ Wx, const float* __restrict__ Wps) {
    int gw   = (blockIdx.x * blockDim.x + threadIdx.x) >> 5;
    int lane = threadIdx.x & 31;
    if (gw >= 3 * HH) return;
    int mat = gw >> 10, row = gw & (HH - 1);
    const float* W = (mat == 0) ? Wh : (mat == 1) ? Ws : Wx;
    float s = 0.f;
    for (int o = lane; o < HH; o += 32) s += W[row * HH + o] * Wps[o];
    #pragma unroll
    for (int d = 16; d; d >>= 1) s += __shfl_down_sync(0xffffffffu, s, d);
    if (lane == 0) ((mat == 0) ? g_vh : (mat == 1) ? g_vs : g_vx)[row] = s;
}

// prefix kernel: hq fp16 conversion + the three per-token gates
__global__ void k_tok(const float* __restrict__ hs, const float* __restrict__ qt,
                      const float* __restrict__ te,
                      const float* __restrict__ bx, const float* __restrict__ Wps,
                      const float* __restrict__ bps,
                      const float* __restrict__ Wgg, const float* __restrict__ bgg,
                      const float* __restrict__ Wmg, const float* __restrict__ bmg,
                      float* out_ps) {
    int tok = blockIdx.x;
    int tid = threadIdx.x;
    const float* h = hs + (size_t)tok * HH;
    const float* q = qt + (size_t)tok * HH;
    const float* e = te + (size_t)tok * HH;
    float sp = 0.f, sg = 0.f, sm = 0.f;
    for (int k = tid; k < HH; k += blockDim.x) {
        float hv = h[k], qv = q[k], ev = e[k];
        g_hqH[(size_t)tok * KK2 + k]      = __float2half_rn(hv);
        g_hqH[(size_t)tok * KK2 + HH + k] = __float2half_rn(qv);
        sp += hv * g_vh[k] + qv * g_vs[k] + ev * g_vx[k] + bx[k] * Wps[k];
        sg += hv * Wgg[k] + qv * Wgg[HH + k];
        sm += hv * Wmg[k] + qv * Wmg[HH + k];
    }
    __shared__ float sh0[32], sh1[32], sh2[32];
    sp = blk_reduce_sum(sp, sh0);
    sg = blk_reduce_sum(sg, sh1);
    sm = blk_reduce_sum(sm, sh2);
    if (tid == 0) {
        float ps = 1.f / (1.f + expf(-(sp + bps[0])));
        float gg = 1.f / (1.f + expf(-(sg + bgg[0])));
        float mg = 1.f / (1.f + expf(-(sm + bmg[0])));
        g_ps[tok] = ps; g_gg[tok] = gg; g_mg[tok] = mg;
        out_ps[tok] = ps;
    }
}

// prefix kernel: qe fp16 conversion
__global__ void k_qe(const float* __restrict__ qt, const float* __restrict__ te) {
    int tok = blockIdx.x;
    int tid = threadIdx.x;
    const float* q = qt + (size_t)tok * HH;
    const float* e = te + (size_t)tok * HH;
    for (int k = tid; k < HH; k += blockDim.x) {
        g_qeH[(size_t)tok * KK2 + k]      = __float2half_rn(q[k]);
        g_qeH[(size_t)tok * KK2 + HH + k] = __float2half_rn(e[k]);
    }
}

__global__ void k_edges(const int* __restrict__ edges) {
    int i = blockIdx.x * blockDim.x + threadIdx.x;
    if (i >= BB * EE) return;
    int b = i / EE, e = i % EE;
    int src = edges[b * 2 * EE + e];
    int dst = edges[b * 2 * EE + EE + e];
    atomicAdd(&g_graphT[b * NN * NN + dst * NN + src], 1.0f);
}

__global__ void k_m() {
    int b = blockIdx.x, n = threadIdx.x;
    if (n >= NN) return;
    float m = 0.f;
    for (int t = 0; t < TT; t++) {
        int bt = b * TT + t;
        float mg = g_mg[bt];
        m = g_cp[(size_t)bt * NN + n] * mg + m * (1.f - mg);
        g_M[(size_t)bt * NN + n] = m;
    }
}

#define GS_TT 16
__global__ void k_gsem() {
    __shared__ float Msh[GS_TT * NN];
    int b = blockIdx.x, t0 = blockIdx.y * GS_TT;
    int tid = threadIdx.x;
    for (int idx = tid; idx < GS_TT * NN; idx += blockDim.x) {
        int tt = idx / NN, j = idx % NN;
        Msh[tt * NN + j] = g_M[(size_t)(b * TT + t0 + tt) * NN + j];
    }
    __syncthreads();
    int i = tid;
    if (i >= NN) return;
    float acc[GS_TT];
    #pragma unroll
    for (int tt = 0; tt < GS_TT; tt++) acc[tt] = 0.f;
    const float* GT = g_graphT + (size_t)b * NN * NN;
    for (int j = 0; j < NN; j++) {
        float g = GT[(size_t)j * NN + i];
        #pragma unroll
        for (int tt = 0; tt < GS_TT; tt++) acc[tt] = fmaf(g, Msh[tt * NN + j], acc[tt]);
    }
    #pragma unroll
    for (int tt = 0; tt < GS_TT; tt++) {
        int bt = b * TT + t0 + tt;
        float gg = g_gg[bt];
        g_pg[(size_t)bt * NN + i] = g_cp[(size_t)bt * NN + i] * gg + acc[tt] * (1.f - gg);
    }
}

__global__ void k_cov(float* out_cov) {
    int bt = blockIdx.x;
    int b = bt / TT;
    int tid = threadIdx.x;
    float ps = g_ps[bt];
    float x = (tid < NN) ? g_pg[(size_t)bt * NN + tid] * ps : -1e30f;
    __shared__ float shm[32], shs[32];
    float mx = blk_reduce_max(x, shm);
    float e = (tid < NN) ? expf(x - mx) : 0.f;
    float s = blk_reduce_sum(e, shs);
    if (tid < NN) atomicAdd(&out_cov[b * NN + tid], e / s);
}

__global__ void k_scatter(const int* __restrict__ nidx, float* __restrict__ out) {
    int i = blockIdx.x * blockDim.x + threadIdx.x;
    if (i >= BT * NN) return;
    int bt = i / NN, n = i % NN;
    atomicAdd(&out[(size_t)bt * VV + nidx[n]], g_pg[i] * g_ps[bt]);
}

// ====== GEMM machinery (R13 skeleton, unchanged) ======
#define GH_BM 256
#define GH_BN 64
#define GH_NB (KK2 / 32)           // 64 k-blocks
#define GH_AP 80
#define GH_AST (GH_BM * GH_AP)     // 20480 per A stage
#define GH_BST (GH_BN * GH_AP)     // 5120 per B buffer
#define GH_SMEM (3 * GH_AST + 2 * GH_BST)   // 71680

__device__ __forceinline__ uint32_t smem_u32(const void* p) {
    uint32_t a;
    asm("{ .reg .u64 t; cvta.to.shared.u64 t, %1; cvt.u32.u64 %0, t; }" : "=r"(a) : "l"(p));
    return a;
}
__device__ __forceinline__ void cp16(uint32_t dst, const void* src) {
    asm volatile("cp.async.cg.shared.global [%0], [%1], 16;" :: "r"(dst), "l"(src));
}

#define LDSM_X4(r, addr) \
    asm volatile("ldmatrix.sync.aligned.m8n8.x4.shared.b16 {%0,%1,%2,%3}, [%4];" \
        : "=r"((r)[0]), "=r"((r)[1]), "=r"((r)[2]), "=r"((r)[3]) : "r"(addr))

#define HMMA(c, a, b0v, b1v) \
    asm volatile("mma.sync.aligned.m16n8k16.row.col.f32.f16.f16.f32 " \
        "{%0,%1,%2,%3}, {%4,%5,%6,%7}, {%8,%9}, {%0,%1,%2,%3};" \
        : "+f"((c)[0]), "+f"((c)[1]), "+f"((c)[2]), "+f"((c)[3]) \
        : "r"((a)[0]), "r"((a)[1]), "r"((a)[2]), "r"((a)[3]), "r"(b0v), "r"(b1v))

// Core mainloop. A = fp16 [BT,KK2]; B = f32 [KK2,LDB] converted inline.
template<int LDB>
__device__ __forceinline__ void gemm_core(const __half* __restrict__ Ah,
                                          const float* __restrict__ Bf,
                                          int m0, int n0, uint32_t sb,
                                          float (&acc)[4][4][4],
                                          uint32_t (&aoff)[4], uint32_t (&boff)[2]) {
    const int tid = threadIdx.x;
    const int bn = tid & 63;
    const int bq = tid >> 6;                 // 0..3, k = bq*8 .. bq*8+7
    const int nn = n0 + bn;
    const int nnc = (nn < LDB) ? nn : (LDB - 1);
    const uint32_t bsts = sb + 3u * GH_AST + (uint32_t)(bn * GH_AP + bq * 16);
    const __half* asrc = Ah + (size_t)m0 * KK2;

    auto cpA = [&](int kb, int s) {
        const uint32_t base = sb + (uint32_t)s * GH_AST;
        const size_t koff = (size_t)kb * 32;
        #pragma unroll
        for (int i = 0; i < 4; i++) {
            int idx = i * 256 + tid;           // 0..1023
            int m = idx >> 2, c = idx & 3;
            cp16(base + (uint32_t)(m * GH_AP + c * 16),
                 (const char*)(asrc + (size_t)m * KK2 + koff) + c * 16);
        }
        asm volatile("cp.async.commit_group;" ::: "memory");
    };
    auto ldgB = [&](float (&rB)[8], int kb) {
        const float* p = Bf + (size_t)(kb * 32 + bq * 8) * LDB + nnc;
        #pragma unroll
        for (int j = 0; j < 8; j++)
            rB[j] = p[(size_t)j * LDB];
    };
    auto stsB = [&](const float (&rB)[8], int buf) {
        __half2 h0 = __floats2half2_rn(rB[0], rB[1]);
        __half2 h1 = __floats2half2_rn(rB[2], rB[3]);
        __half2 h2 = __floats2half2_rn(rB[4], rB[5]);
        __half2 h3 = __floats2half2_rn(rB[6], rB[7]);
        asm volatile("st.shared.v4.b32 [%0], {%1, %2, %3, %4};"
                     :: "r"(bsts + (uint32_t)buf * GH_BST),
                        "r"(*(uint32_t*)&h0), "r"(*(uint32_t*)&h1),
                        "r"(*(uint32_t*)&h2), "r"(*(uint32_t*)&h3));
    };
    auto compute = [&](uint32_t As, uint32_t Bs) {
        #pragma unroll
        for (int ks = 0; ks < 2; ks++) {
            uint32_t a[4][4], bf[2][4];
            #pragma unroll
            for (int p = 0; p < 2; p++)
                LDSM_X4(bf[p], Bs + boff[p] + (uint32_t)(ks * 32));
            #pragma unroll
            for (int mi = 0; mi < 4; mi++)
                LDSM_X4(a[mi], As + aoff[mi] + (uint32_t)(ks * 32));
            #pragma unroll
            for (int mi = 0; mi < 4; mi++)
                #pragma unroll
                for (int p = 0; p < 2; p++) {
                    HMMA(acc[mi][2 * p],     a[mi], bf[p][0], bf[p][1]);
                    HMMA(acc[mi][2 * p + 1], a[mi], bf[p][2], bf[p][3]);
                }
        }
    };

    float rBa[8], rBb[8];
    ldgB(rBa, 0);
    ldgB(rBb, 1);
    cpA(0, 0);
    cpA(1, 1);

    int stC = 0, stL = 2;
    #pragma unroll 1
    for (int kb = 0; kb < GH_NB; kb += 2) {
        stsB(rBa, 0);
        if (kb + 2 < GH_NB) ldgB(rBa, kb + 2);
        asm volatile("cp.async.wait_group 1;" ::: "memory");
        __syncthreads();
        if (kb + 2 < GH_NB) {
            cpA(kb + 2, stL);
            stL = (stL == 2) ? 0 : stL + 1;
        }
        compute(sb + (uint32_t)stC * GH_AST, sb + 3u * GH_AST);
        stC = (stC == 2) ? 0 : stC + 1;

        stsB(rBb, 1);
        if (kb + 3 < GH_NB) ldgB(rBb, kb + 3);
        if (kb + 2 < GH_NB)
            asm volatile("cp.async.wait_group 1;" ::: "memory");
        else
            asm volatile("cp.async.wait_group 0;" ::: "memory");
        __syncthreads();
        if (kb + 3 < GH_NB) {
            cpA(kb + 3, stL);
            stL = (stL == 2) ? 0 : stL + 1;
        }
        compute(sb + (uint32_t)stC * GH_AST, sb + 3u * GH_AST + GH_BST);
        stC = (stC == 2) ? 0 : stC + 1;
    }
}

__device__ __forceinline__ void gemm_lane_setup(int lane, int wm, int wn,
                                                uint32_t (&aoff)[4], uint32_t (&boff)[2]) {
    const int a_row  = (lane & 7) + ((lane >> 3) & 1) * 8;
    const int a_koff = ((lane >> 4) & 1) * 16;
    const int b_row  = (lane & 7) + ((lane >> 4) & 1) * 8;
    const int b_koff = ((lane >> 3) & 1) * 16;
    #pragma unroll
    for (int mi = 0; mi < 4; mi++)
        aoff[mi] = (uint32_t)((wm + mi * 16 + a_row) * GH_AP + a_koff);
    #pragma unroll
    for (int p = 0; p < 2; p++)
        boff[p] = (uint32_t)((wn + p * 16 + b_row) * GH_AP + b_koff);
}

// ---- big GEMM: out = (hq @ Wg + bg) * (1 - ps) ----
__global__ __launch_bounds__(256, 2)
void k_gemm_h(const float* __restrict__ Wg, const float* __restrict__ bg,
              float* __restrict__ out) {
    extern __shared__ char smc[];
    const uint32_t sb = smem_u32(smc);
    const int lane = threadIdx.x & 31, wid = threadIdx.x >> 5;
    const int m0 = blockIdx.x * GH_BM;
    const int n0 = blockIdx.y * GH_BN;
    const int wm = (wid & 3) * 64, wn = (wid >> 2) * 32;
    const int g = lane >> 2, t = lane & 3;

    uint32_t aoff[4], boff[2];
    gemm_lane_setup(lane, wm, wn, aoff, boff);

    float acc[4][4][4];
    #pragma unroll
    for (int mi = 0; mi < 4; mi++)
        #pragma unroll
        for (int nj = 0; nj < 4; nj++)
            #pragma unroll
            for (int q = 0; q < 4; q++) acc[mi][nj][q] = 0.f;

    gemm_core<VV>(g_hqH, Wg, m0, n0, sb, acc, aoff, boff);

    #pragma unroll
    for (int mi = 0; mi < 4; mi++) {
        int m = m0 + wm + mi * 16 + g;
        float s0 = 1.f - g_ps[m];
        float s1 = 1.f - g_ps[m + 8];
        #pragma unroll
        for (int nj = 0; nj < 4; nj++) {
            int n = n0 + wn + nj * 8 + t * 2;
            if (n < VV) {
                float bgv = bg[n];
                out[(size_t)m * VV + n]       = (acc[mi][nj][0] + bgv) * s0;
                out[(size_t)(m + 8) * VV + n] = (acc[mi][nj][2] + bgv) * s1;
            }
            if (n + 1 < VV) {
                float bgv = bg[n + 1];
                out[(size_t)m * VV + n + 1]       = (acc[mi][nj][1] + bgv) * s0;
                out[(size_t)(m + 8) * VV + n + 1] = (acc[mi][nj][3] + bgv) * s1;
            }
        }
    }
}

// ---- cp GEMM: g_cp = qe @ Wc + bc (10 CTAs; launched BEFORE big GEMM) ----
__global__ __launch_bounds__(256, 2)
void k_cp_h(const float* __restrict__ Wc, const float* __restrict__ bc) {
    extern __shared__ char smc[];
    const uint32_t sb = smem_u32(smc);
    const int lane = threadIdx.x & 31, wid = threadIdx.x >> 5;
    const int m0 = blockIdx.x * GH_BM;
    const int n0 = blockIdx.y * GH_BN;
    const int wm = (wid & 3) * 64, wn = (wid >> 2) * 32;
    const int g = lane >> 2, t = lane & 3;

    uint32_t aoff[4], boff[2];
    gemm_lane_setup(lane, wm, wn, aoff, boff);

    float acc[4][4][4];
    #pragma unroll
    for (int mi = 0; mi < 4; mi++)
        #pragma unroll
        for (int nj = 0; nj < 4; nj++)
            #pragma unroll
            for (int q = 0; q < 4; q++) acc[mi][nj][q] = 0.f;

    gemm_core<NN>(g_qeH, Wc, m0, n0, sb, acc, aoff, boff);

    #pragma unroll
    for (int mi = 0; mi < 4; mi++) {
        int m = m0 + wm + mi * 16 + g;
        #pragma unroll
        for (int nj = 0; nj < 4; nj++) {
            int n = n0 + wn + nj * 8 + t * 2;
            if (n < NN) {
                g_cp[(size_t)m * NN + n]       = acc[mi][nj][0] + bc[n];
                g_cp[(size_t)(m + 8) * NN + n] = acc[mi][nj][2] + bc[n];
            }
            if (n + 1 < NN) {
                g_cp[(size_t)m * NN + n + 1]       = acc[mi][nj][1] + bc[n + 1];
                g_cp[(size_t)(m + 8) * NN + n + 1] = acc[mi][nj][3] + bc[n + 1];
            }
        }
    }
}

// ---------------- launch: cp GEMM first (side stream), tail overlapped -----
extern "C" void kernel_launch(void* const* d_in, const int* in_sizes, int n_in,
                              void* d_out, int out_size) {
    const float* hs   = (const float*)d_in[0];
    const float* qt   = (const float*)d_in[1];
    const float* te   = (const float*)d_in[2];
    const int*   edges= (const int*)  d_in[3];
    const int*   nidx = (const int*)  d_in[4];
    const float* Wg   = (const float*)d_in[5];
    const float* bg   = (const float*)d_in[6];
    const float* Wh   = (const float*)d_in[7];
    const float* Ws   = (const float*)d_in[8];
    const float* Wx   = (const float*)d_in[9];
    const float* bx   = (const float*)d_in[10];
    const float* Wps  = (const float*)d_in[11];
    const float* bps  = (const float*)d_in[12];
    const float* Wc   = (const float*)d_in[13];
    const float* bc   = (const float*)d_in[14];
    const float* Wgg  = (const float*)d_in[15];
    const float* bgg  = (const float*)d_in[16];
    const float* Wmg  = (const float*)d_in[17];
    const float* bmg  = (const float*)d_in[18];

    float* out    = (float*)d_out;
    float* outCov = out + (size_t)BT * VV;
    float* outPs  = outCov + BB * NN;

    cudaFuncSetAttribute(k_gemm_h, cudaFuncAttributeMaxDynamicSharedMemorySize, GH_SMEM);
    cudaFuncSetAttribute(k_cp_h,   cudaFuncAttributeMaxDynamicSharedMemorySize, GH_SMEM);

    // Fresh side stream + events each call (host objects only; no device mem).
    cudaStream_t s1;
    cudaStreamCreateWithFlags(&s1, cudaStreamNonBlocking);
    cudaEvent_t evFork, evJoin;
    cudaEventCreateWithFlags(&evFork, cudaEventDisableTiming);
    cudaEventCreateWithFlags(&evJoin, cudaEventDisableTiming);

    // ---- prefix (main stream) ----
    k_vec<<<(3 * HH * 32 + 255) / 256, 256>>>(Wh, Ws, Wx, Wps);
    k_tok<<<BT, 256>>>(hs, qt, te, bx, Wps, bps, Wgg, bgg, Wmg, bmg, outPs);
    k_qe<<<BT, 256>>>(qt, te);
    cudaEventRecord(evFork, 0);
    cudaStreamWaitEvent(s1, evFork, 0);

    // ---- side stream: cp GEMM FIRST (launch-order placement => its 10 CTAs
    //      grab SM slots before the 1572-CTA big GEMM fills the machine),
    //      then graph build + the whole tail chain, all overlapping branch A.
    k_cp_h<<<dim3(BT / GH_BM, (NN + GH_BN - 1) / GH_BN), 256, GH_SMEM, s1>>>(Wc, bc);
    k_zero<<<(BB*NN*NN + 255) / 256, 256, 0, s1>>>(outCov);
    k_edges<<<(BB*EE + 255) / 256, 256, 0, s1>>>(edges);
    k_m<<<BB, 320, 0, s1>>>();
    k_gsem<<<dim3(BB, TT / GS_TT), 320, 0, s1>>>();
    k_cov<<<BT, 320, 0, s1>>>(outCov);
    cudaEventRecord(evJoin, s1);

    // ---- branch A (main stream): big GEMM ----
    k_gemm_h<<<dim3(BT / GH_BM, (VV + GH_BN - 1) / GH_BN), 256, GH_SMEM>>>(Wg, bg, out);

    // ---- join: scatter needs big GEMM's `out` and branch B's `g_pg` ----
    cudaStreamWaitEvent(0, evJoin, 0);
    k_scatter<<<(BT*NN + 255) / 256, 256>>>(nidx, out);
}